// round 11
// baseline (speedup 1.0000x reference)
#include <cuda_runtime.h>
#include <math.h>
#include <stdint.h>

#define H  1024
#define B  64
#define L  1024
#define VP 32000
#define VC 32000

typedef unsigned long long ull;

// ---- flash attention config ----
#define CS   8
#define LPW  (L / CS / 8)
#define NPART 64

// ---- tf32 GEMM config ----
#define TVL   128
#define KCL   32
#define PITCH 36
#define SM_GEMM3 ((2 * 2 * TVL * PITCH + 2 * 2 * B * PITCH) * 4)
// logits tensor flavor: 3-stage cp.async
#define STAGES 3
#define STG_FLOATS (TVL * PITCH + B * PITCH)
#define SM_LOG (STAGES * STG_FLOATS * 4)     // 82944 B (max of both flavors)

#define GRU_ROWS   6144
#define GRU_SPLITS 2
#define CAT_ROWS   1024
#define CAT_SPLITS 4

// ---- scratch ----
__device__ __align__(16) float g_xh[2 * B * H];
__device__ __align__(16) float g_gatep[GRU_SPLITS * GRU_ROWS * B];
__device__ __align__(16) float g_hnew[B * H];
__device__ __align__(16) float g_hc[B * 2 * H];
__device__ __align__(16) float g_scores[B * L];
__device__ __align__(16) float g_ctxpart[B * NPART * H];
__device__ float g_pm[B * NPART];
__device__ float g_ps[B * NPART];
__device__ __align__(16) float g_cpart[CAT_SPLITS * CAT_ROWS * B];
__device__ __align__(16) float g_concat[B * H];   // pre-rounded tf32

__device__ __forceinline__ float warp_sum(float v) {
#pragma unroll
    for (int o = 16; o; o >>= 1) v += __shfl_xor_sync(0xffffffffu, v, o);
    return v;
}
__device__ __forceinline__ float f2tf32f(float x) {
    uint32_t u; asm("cvt.rna.tf32.f32 %0, %1;" : "=r"(u) : "f"(x));
    return __uint_as_float(u);
}
__device__ __forceinline__ uint32_t f2tf32u(float x) {
    uint32_t u; asm("cvt.rna.tf32.f32 %0, %1;" : "=r"(u) : "f"(x));
    return u;
}
__device__ __forceinline__ void mma_tf32(float* c, const uint32_t* a,
                                         uint32_t b0, uint32_t b1) {
    asm volatile(
        "mma.sync.aligned.m16n8k8.row.col.f32.tf32.tf32.f32 "
        "{%0,%1,%2,%3}, {%4,%5,%6,%7}, {%8,%9}, {%0,%1,%2,%3};"
        : "+f"(c[0]), "+f"(c[1]), "+f"(c[2]), "+f"(c[3])
        : "r"(a[0]), "r"(a[1]), "r"(a[2]), "r"(a[3]), "r"(b0), "r"(b1));
}
__device__ __forceinline__ void cp_async16(uint32_t dst, const void* src) {
    asm volatile("cp.async.cg.shared.global [%0], [%1], 16;" :: "r"(dst), "l"(src));
}
#define CP_COMMIT() asm volatile("cp.async.commit_group;" ::: "memory")
#define CP_WAIT(n)  asm volatile("cp.async.wait_group %0;" :: "n"(n) : "memory")

__device__ __forceinline__ ull pack2(float a, float b) {
    ull r; asm("mov.b64 %0, {%1,%2};" : "=l"(r) : "f"(a), "f"(b)); return r;
}
__device__ __forceinline__ void unpack2(ull v, float& a, float& b) {
    asm("mov.b64 {%0,%1}, %2;" : "=f"(a), "=f"(b) : "l"(v));
}
__device__ __forceinline__ ull fma2(ull a, ull b, ull c) {
    ull d; asm("fma.rn.f32x2 %0, %1, %2, %3;" : "=l"(d) : "l"(a), "l"(b), "l"(c));
    return d;
}

// ---------------------------------------------------------------------------
// 0) pack x and h_prev
// ---------------------------------------------------------------------------
__global__ void pack_xh_kernel(const int* __restrict__ seq,
                               const float* __restrict__ hprev,
                               const float* __restrict__ emb) {
    int b = blockIdx.x, tid = threadIdx.x;
    ((float4*)(g_xh + (size_t)b * H))[tid] =
        ((const float4*)(emb + (size_t)seq[b] * H))[tid];
    ((float4*)(g_xh + (size_t)(B + b) * H))[tid] =
        ((const float4*)(hprev + (size_t)b * H))[tid];
}

// ---------------------------------------------------------------------------
// Generic SPLIT-3 tf32 GEMM (R10, measured-good accuracy)
// ---------------------------------------------------------------------------
__global__ __launch_bounds__(256) void gemm_part(
        const float* __restrict__ A0, const float* __restrict__ A1,
        const float* __restrict__ X0, const float* __restrict__ X1,
        float* __restrict__ outp, int ldA, int kPerSplit, int halfBlocks,
        int totalRows) {
    extern __shared__ float smf[];
    float* Wt = smf;
    float* Xt = smf + 2 * 2 * TVL * PITCH;

    int tid = threadIdx.x;
    int wid = tid >> 5, lane = tid & 31;
    int grp = lane >> 2, tig = lane & 3;
    int warpM = wid & 3, warpN = wid >> 2;

    const float* A = A0; const float* X = X0;
    int blk = blockIdx.x;
    int outRowBase = blk * TVL;
    if (halfBlocks > 0 && blk >= halfBlocks) { A = A1; X = X1; blk -= halfBlocks; }
    int a0 = blk * TVL;
    int kOff = blockIdx.y * kPerSplit;
    int nt = kPerSplit / KCL;

#define WP_(buf, part) (Wt + ((buf) * 2 + (part)) * TVL * PITCH)
#define XP_(buf, part) (Xt + ((buf) * 2 + (part)) * B * PITCH)

    float acc[2][4][4];
#pragma unroll
    for (int i = 0; i < 2; i++)
#pragma unroll
        for (int j = 0; j < 4; j++)
#pragma unroll
            for (int q = 0; q < 4; q++) acc[i][j][q] = 0.f;

#pragma unroll
    for (int r = 0; r < 4; r++) {
        int f = tid + r * 256;
        int v = f >> 3, kq = f & 7;
        float4 w4 = *(const float4*)(A + (size_t)(a0 + v) * ldA + kOff + kq * 4);
        float hx = f2tf32f(w4.x), hy = f2tf32f(w4.y), hz = f2tf32f(w4.z), hw = f2tf32f(w4.w);
        *(float4*)&WP_(0, 0)[v * PITCH + kq * 4] = make_float4(hx, hy, hz, hw);
        *(float4*)&WP_(0, 1)[v * PITCH + kq * 4] =
            make_float4(f2tf32f(w4.x - hx), f2tf32f(w4.y - hy),
                        f2tf32f(w4.z - hz), f2tf32f(w4.w - hw));
    }
#pragma unroll
    for (int r = 0; r < 2; r++) {
        int f = tid + r * 256;
        int xb = f >> 3, kq = f & 7;
        float4 x4 = *(const float4*)(X + (size_t)xb * ldA + kOff + kq * 4);
        float hx = f2tf32f(x4.x), hy = f2tf32f(x4.y), hz = f2tf32f(x4.z), hw = f2tf32f(x4.w);
        *(float4*)&XP_(0, 0)[xb * PITCH + kq * 4] = make_float4(hx, hy, hz, hw);
        *(float4*)&XP_(0, 1)[xb * PITCH + kq * 4] =
            make_float4(f2tf32f(x4.x - hx), f2tf32f(x4.y - hy),
                        f2tf32f(x4.z - hz), f2tf32f(x4.w - hw));
    }
    __syncthreads();

    for (int t = 0; t < nt; t++) {
        int cur = t & 1;
        float* WH = WP_(cur, 0); float* WL = WP_(cur, 1);
        float* XH = XP_(cur, 0); float* XL = XP_(cur, 1);
        float4 wpre[4], xpre[2];
        if (t + 1 < nt) {
            int kc = kOff + (t + 1) * KCL;
#pragma unroll
            for (int r = 0; r < 4; r++) {
                int f = tid + r * 256;
                int v = f >> 3, kq = f & 7;
                wpre[r] = *(const float4*)(A + (size_t)(a0 + v) * ldA + kc + kq * 4);
            }
#pragma unroll
            for (int r = 0; r < 2; r++) {
                int f = tid + r * 256;
                int xb = f >> 3, kq = f & 7;
                xpre[r] = *(const float4*)(X + (size_t)xb * ldA + kc + kq * 4);
            }
        }
#pragma unroll
        for (int ks = 0; ks < KCL / 8; ks++) {
            int k0 = ks * 8 + tig;
            uint32_t aH[2][4], aL[2][4];
#pragma unroll
            for (int mf = 0; mf < 2; mf++) {
                int mm = warpM * 32 + mf * 16 + grp;
                aH[mf][0] = __float_as_uint(WH[mm * PITCH + k0]);
                aH[mf][1] = __float_as_uint(WH[(mm + 8) * PITCH + k0]);
                aH[mf][2] = __float_as_uint(WH[mm * PITCH + k0 + 4]);
                aH[mf][3] = __float_as_uint(WH[(mm + 8) * PITCH + k0 + 4]);
                aL[mf][0] = __float_as_uint(WL[mm * PITCH + k0]);
                aL[mf][1] = __float_as_uint(WL[(mm + 8) * PITCH + k0]);
                aL[mf][2] = __float_as_uint(WL[mm * PITCH + k0 + 4]);
                aL[mf][3] = __float_as_uint(WL[(mm + 8) * PITCH + k0 + 4]);
            }
#pragma unroll
            for (int nf = 0; nf < 4; nf++) {
                int n = warpN * 32 + nf * 8 + grp;
                uint32_t bH0 = __float_as_uint(XH[n * PITCH + k0]);
                uint32_t bH1 = __float_as_uint(XH[n * PITCH + k0 + 4]);
                uint32_t bL0 = __float_as_uint(XL[n * PITCH + k0]);
                uint32_t bL1 = __float_as_uint(XL[n * PITCH + k0 + 4]);
#pragma unroll
                for (int mf = 0; mf < 2; mf++) {
                    mma_tf32(acc[mf][nf], aH[mf], bH0, bH1);
                    mma_tf32(acc[mf][nf], aH[mf], bL0, bL1);
                    mma_tf32(acc[mf][nf], aL[mf], bH0, bH1);
                }
            }
        }
        if (t + 1 < nt) {
            int nxt = cur ^ 1;
#pragma unroll
            for (int r = 0; r < 4; r++) {
                int f = tid + r * 256;
                int v = f >> 3, kq = f & 7;
                float hx = f2tf32f(wpre[r].x), hy = f2tf32f(wpre[r].y);
                float hz = f2tf32f(wpre[r].z), hw = f2tf32f(wpre[r].w);
                *(float4*)&WP_(nxt, 0)[v * PITCH + kq * 4] = make_float4(hx, hy, hz, hw);
                *(float4*)&WP_(nxt, 1)[v * PITCH + kq * 4] =
                    make_float4(f2tf32f(wpre[r].x - hx), f2tf32f(wpre[r].y - hy),
                                f2tf32f(wpre[r].z - hz), f2tf32f(wpre[r].w - hw));
            }
#pragma unroll
            for (int r = 0; r < 2; r++) {
                int f = tid + r * 256;
                int xb = f >> 3, kq = f & 7;
                float hx = f2tf32f(xpre[r].x), hy = f2tf32f(xpre[r].y);
                float hz = f2tf32f(xpre[r].z), hw = f2tf32f(xpre[r].w);
                *(float4*)&XP_(nxt, 0)[xb * PITCH + kq * 4] = make_float4(hx, hy, hz, hw);
                *(float4*)&XP_(nxt, 1)[xb * PITCH + kq * 4] =
                    make_float4(f2tf32f(xpre[r].x - hx), f2tf32f(xpre[r].y - hy),
                                f2tf32f(xpre[r].z - hz), f2tf32f(xpre[r].w - hw));
            }
        }
        __syncthreads();
    }
#undef WP_
#undef XP_

    float* o = outp + (size_t)blockIdx.y * totalRows * B;
#pragma unroll
    for (int mf = 0; mf < 2; mf++) {
        int vr = outRowBase + warpM * 32 + mf * 16 + grp;
#pragma unroll
        for (int nf = 0; nf < 4; nf++) {
            int bcol = warpN * 32 + nf * 8 + 2 * tig;
            o[(size_t)vr * B + bcol]           = acc[mf][nf][0];
            o[(size_t)vr * B + bcol + 1]       = acc[mf][nf][1];
            o[(size_t)(vr + 8) * B + bcol]     = acc[mf][nf][2];
            o[(size_t)(vr + 8) * B + bcol + 1] = acc[mf][nf][3];
        }
    }
}

// ---------------------------------------------------------------------------
// gate combine -> h_new
// ---------------------------------------------------------------------------
__global__ void gru_gate_kernel(const float* __restrict__ hprev,
                                const float* __restrict__ b_ih,
                                const float* __restrict__ b_hh,
                                float* __restrict__ hidden_out) {
    int tid = threadIdx.x;
    int b = tid & 63;
    int i = blockIdx.x * 4 + (tid >> 6);
#define GP(row) (g_gatep[(size_t)(row) * B + b] + \
                 g_gatep[(size_t)(GRU_ROWS + (row)) * B + b])
    float gir = GP(i),          giz = GP(H + i),      gin = GP(2 * H + i);
    float ghr = GP(3 * H + i),  ghz = GP(4 * H + i),  ghn = GP(5 * H + i);
#undef GP
    float r = 1.f / (1.f + expf(-(gir + b_ih[i] + ghr + b_hh[i])));
    float z = 1.f / (1.f + expf(-(giz + b_ih[H + i] + ghz + b_hh[H + i])));
    float n = tanhf(gin + b_ih[2 * H + i] + r * (ghn + b_hh[2 * H + i]));
    float hv = hprev[(size_t)b * H + i];
    float hn = (1.f - z) * n + z * hv;
    g_hnew[(size_t)b * H + i] = hn;
    g_hc[(size_t)b * 2 * H + i] = hn;
    hidden_out[(size_t)b * H + i] = hn;
}

// ---------------------------------------------------------------------------
// flash attention (measured 46.9us @ 76% DRAM)
// ---------------------------------------------------------------------------
__global__ __launch_bounds__(256) void flash2_kernel(const float* __restrict__ enc) {
    int b = blockIdx.x, ch = blockIdx.y;
    int w = threadIdx.x >> 5, lane = threadIdx.x & 31;
    int l0 = ch * (L / CS) + w * LPW;

    const float4* hb = (const float4*)(g_hnew + (size_t)b * H);
    float4 h[8];
#pragma unroll
    for (int q = 0; q < 8; q++) h[q] = hb[lane + q * 32];

    float4 acc[8];
#pragma unroll
    for (int q = 0; q < 8; q++) acc[q] = make_float4(0.f, 0.f, 0.f, 0.f);
    float m = -1e30f, ssum = 0.f;

    for (int j = 0; j < LPW; j++) {
        int l = l0 + j;
        const float4* er = (const float4*)(enc + ((size_t)l * B + b) * H);
        float4 e[8];
        float d = 0.f;
#pragma unroll
        for (int q = 0; q < 8; q++) {
            e[q] = er[lane + q * 32];
            d += e[q].x * h[q].x + e[q].y * h[q].y + e[q].z * h[q].z + e[q].w * h[q].w;
        }
        d = warp_sum(d);
        if (lane == 0) g_scores[b * L + l] = d;
        float nm = fmaxf(m, d);
        float sc = expf(m - nm);
        float p = expf(d - nm);
        ssum = ssum * sc + p;
#pragma unroll
        for (int q = 0; q < 8; q++) {
            acc[q].x = acc[q].x * sc + p * e[q].x;
            acc[q].y = acc[q].y * sc + p * e[q].y;
            acc[q].z = acc[q].z * sc + p * e[q].z;
            acc[q].w = acc[q].w * sc + p * e[q].w;
        }
        m = nm;
    }

    int pidx = b * NPART + ch * 8 + w;
    float4* pp = (float4*)(g_ctxpart + (size_t)pidx * H);
#pragma unroll
    for (int q = 0; q < 8; q++) pp[lane + q * 32] = acc[q];
    if (lane == 0) { g_pm[pidx] = m; g_ps[pidx] = ssum; }
}

__global__ void ctx_combine2_kernel() {
    int b = blockIdx.x, tid = threadIdx.x;
    __shared__ float sm[NPART], sw[NPART];
    if (tid < NPART) sm[tid] = g_pm[b * NPART + tid];
    __syncthreads();
    float gm = -1e30f;
#pragma unroll 8
    for (int c = 0; c < NPART; c++) gm = fmaxf(gm, sm[c]);
    if (tid < NPART) sw[tid] = expf(sm[tid] - gm);
    __syncthreads();
    float S = 0.f;
#pragma unroll 8
    for (int c = 0; c < NPART; c++) S += g_ps[b * NPART + c] * sw[c];
    float inv = 1.f / S;
    float4 a = make_float4(0.f, 0.f, 0.f, 0.f);
    for (int c = 0; c < NPART; c++) {
        float wgt = sw[c];
        float4 p = ((const float4*)(g_ctxpart + ((size_t)(b * NPART + c)) * H))[tid];
        a.x += wgt * p.x; a.y += wgt * p.y; a.z += wgt * p.z; a.w += wgt * p.w;
    }
    a.x *= inv; a.y *= inv; a.z *= inv; a.w *= inv;
    ((float4*)(g_hc + (size_t)b * 2 * H + H))[tid] = a;
}

// ---------------------------------------------------------------------------
// concat reduce + tanh; stores g_concat pre-rounded tf32
// ---------------------------------------------------------------------------
__global__ void cat_reduce_kernel(const float* __restrict__ cb) {
    int tid = threadIdx.x;
    int b = tid & 63;
    int i = blockIdx.x * 4 + (tid >> 6);
    float s = 0.f;
#pragma unroll
    for (int y = 0; y < CAT_SPLITS; y++)
        s += g_cpart[(size_t)(y * CAT_ROWS + i) * B + b];
    g_concat[(size_t)b * H + i] = f2tf32f(tanhf(s + cb[i]));
}

// ---------------------------------------------------------------------------
// logits HYBRID: tensor-pipe blocks (tf32 MMA) compute the pinyin head,
// FMA-pipe blocks (packed f32x2 FFMA) compute the char head, interleaved
// 1:2 by blockIdx so both pipes run concurrently on every SM.
// ---------------------------------------------------------------------------
__global__ __launch_bounds__(256) void logits_hybrid(
        const float* __restrict__ wp, const float* __restrict__ bp,
        const float* __restrict__ wc, const float* __restrict__ bc,
        float* __restrict__ out) {
    extern __shared__ float smf[];
    int tid = threadIdx.x;
    int bid = blockIdx.x;
    const int NT = H / KCL;   // 32

    if (bid % 3 == 0) {
        // ================= TENSOR FLAVOR (pinyin head) =================
        int tIdx = bid / 3;                 // 0..249
        int v0 = tIdx * TVL;
        const float* W = wp; const float* bias = bp; float* obase = out;

        int wid = tid >> 5, lane = tid & 31;
        int grp = lane >> 2, tig = lane & 3;
        int warpM = wid & 3, warpN = wid >> 2;

        float acc[2][4][4];
#pragma unroll
        for (int i = 0; i < 2; i++)
#pragma unroll
            for (int j = 0; j < 4; j++)
#pragma unroll
                for (int q = 0; q < 4; q++) acc[i][j][q] = 0.f;

        auto issue = [&](int t, int slot) {
            float* Ws = smf + slot * STG_FLOATS;
            float* Xs = Ws + TVL * PITCH;
            int kc = t * KCL;
#pragma unroll
            for (int r = 0; r < 4; r++) {
                int f = tid + r * 256;
                int v = f >> 3, kq = f & 7;
                uint32_t dst = (uint32_t)__cvta_generic_to_shared(&Ws[v * PITCH + kq * 4]);
                cp_async16(dst, W + (size_t)(v0 + v) * H + kc + kq * 4);
            }
#pragma unroll
            for (int r = 0; r < 2; r++) {
                int f = tid + r * 256;
                int xb = f >> 3, kq = f & 7;
                uint32_t dst = (uint32_t)__cvta_generic_to_shared(&Xs[xb * PITCH + kq * 4]);
                cp_async16(dst, g_concat + (size_t)xb * H + kc + kq * 4);
            }
            CP_COMMIT();
        };

        issue(0, 0);
        issue(1, 1);

        for (int t = 0; t < NT; t++) {
            if (t + 2 < NT) { CP_WAIT(1); } else { CP_WAIT(0); }
            __syncthreads();
            if (t + 2 < NT) issue(t + 2, (t + 2) % STAGES);

            float* Wc = smf + (t % STAGES) * STG_FLOATS;
            float* Xc = Wc + TVL * PITCH;
#pragma unroll
            for (int ks = 0; ks < KCL / 8; ks++) {
                int k0 = ks * 8 + tig;
                uint32_t a[2][4];
#pragma unroll
                for (int mf = 0; mf < 2; mf++) {
                    int mm = warpM * 32 + mf * 16 + grp;
                    a[mf][0] = f2tf32u(Wc[mm * PITCH + k0]);
                    a[mf][1] = f2tf32u(Wc[(mm + 8) * PITCH + k0]);
                    a[mf][2] = f2tf32u(Wc[mm * PITCH + k0 + 4]);
                    a[mf][3] = f2tf32u(Wc[(mm + 8) * PITCH + k0 + 4]);
                }
#pragma unroll
                for (int nf = 0; nf < 4; nf++) {
                    int n = warpN * 32 + nf * 8 + grp;
                    uint32_t b0 = __float_as_uint(Xc[n * PITCH + k0]);
                    uint32_t b1 = __float_as_uint(Xc[n * PITCH + k0 + 4]);
                    mma_tf32(acc[0][nf], a[0], b0, b1);
                    mma_tf32(acc[1][nf], a[1], b0, b1);
                }
            }
            __syncthreads();
        }

#pragma unroll
        for (int mf = 0; mf < 2; mf++) {
            int vr = v0 + warpM * 32 + mf * 16 + grp;
            float b0 = bias[vr], b1 = bias[vr + 8];
#pragma unroll
            for (int nf = 0; nf < 4; nf++) {
                int bcol = warpN * 32 + nf * 8 + 2 * tig;
                obase[(size_t)bcol * VP + vr]           = acc[mf][nf][0] + b0;
                obase[(size_t)(bcol + 1) * VP + vr]     = acc[mf][nf][1] + b0;
                obase[(size_t)bcol * VP + vr + 8]       = acc[mf][nf][2] + b1;
                obase[(size_t)(bcol + 1) * VP + vr + 8] = acc[mf][nf][3] + b1;
            }
        }
    } else {
        // ================= FFMA FLAVOR (char head) =================
        int fIdx = bid - bid / 3 - 1;       // 0..499
        int vloc = fIdx * 64;               // local row in char head
        const float* W = wc; const float* bias = bc;
        float* obase = out + (size_t)B * VP;

        // smem layout: rawW[2][64*36] | rawX[2][64*36] | Wp[32*34] ull | Xd[32*66] ull
        float* rawW = smf;
        float* rawX = smf + 2 * 64 * 36;
        ull* Wp = (ull*)(smf + 4 * 64 * 36);
        ull* Xd = Wp + 32 * 34;

        int bgrp = tid & 15;     // 4 batch cols each
        int vgrp = tid >> 4;     // 4 vocab rows each

        ull acc2[2][4];
#pragma unroll
        for (int i = 0; i < 2; i++)
#pragma unroll
            for (int j = 0; j < 4; j++) acc2[i][j] = 0ull;

        auto issueF = [&](int t, int slot) {
            float* Ws = rawW + slot * 64 * 36;
            float* Xs = rawX + slot * 64 * 36;
            int kc = t * KCL;
#pragma unroll
            for (int r = 0; r < 2; r++) {
                int f = tid + r * 256;       // 0..511
                int v = f >> 3, kq = f & 7;
                uint32_t dw = (uint32_t)__cvta_generic_to_shared(&Ws[v * 36 + kq * 4]);
                cp_async16(dw, W + (size_t)(vloc + v) * H + kc + kq * 4);
                uint32_t dx = (uint32_t)__cvta_generic_to_shared(&Xs[v * 36 + kq * 4]);
                cp_async16(dx, g_concat + (size_t)v * H + kc + kq * 4);
            }
            CP_COMMIT();
        };

        issueF(0, 0);
        issueF(1, 1);

        for (int t = 0; t < NT; t++) {
            if (t + 2 < NT) { CP_WAIT(1); } else { CP_WAIT(0); }
            __syncthreads();                  // raw[t&1] ready; prior compute done

            // pack raw -> Wp / Xd
            float* Ws = rawW + (t & 1) * 64 * 36;
            float* Xs = rawX + (t & 1) * 64 * 36;
#pragma unroll
            for (int j = 0; j < 4; j++) {
                int u = tid * 4 + j;          // 0..1023
                int k = u >> 5, vpair = u & 31;
                Wp[k * 34 + vpair] = pack2(Ws[(2 * vpair) * 36 + k],
                                           Ws[(2 * vpair + 1) * 36 + k]);
            }
#pragma unroll
            for (int j = 0; j < 8; j++) {
                int u = tid * 8 + j;          // 0..2047
                int k = u >> 6, bb = u & 63;
                float x = Xs[bb * 36 + k];
                Xd[k * 66 + bb] = pack2(x, x);
            }
            __syncthreads();                  // packed ready; raw[t&1] free
            if (t + 2 < NT) issueF(t + 2, t & 1);

            // compute on packed tile
#pragma unroll
            for (int k = 0; k < KCL; k++) {
                ulonglong2 w2  = *(const ulonglong2*)&Wp[k * 34 + vgrp * 2];
                ulonglong2 x01 = *(const ulonglong2*)&Xd[k * 66 + bgrp * 4];
                ulonglong2 x23 = *(const ulonglong2*)&Xd[k * 66 + bgrp * 4 + 2];
                acc2[0][0] = fma2(w2.x, x01.x, acc2[0][0]);
                acc2[0][1] = fma2(w2.x, x01.y, acc2[0][1]);
                acc2[0][2] = fma2(w2.x, x23.x, acc2[0][2]);
                acc2[0][3] = fma2(w2.x, x23.y, acc2[0][3]);
                acc2[1][0] = fma2(w2.y, x01.x, acc2[1][0]);
                acc2[1][1] = fma2(w2.y, x01.y, acc2[1][1]);
                acc2[1][2] = fma2(w2.y, x23.x, acc2[1][2]);
                acc2[1][3] = fma2(w2.y, x23.y, acc2[1][3]);
            }
            __syncthreads();                  // protect packed before next pack
        }

        // epilogue: rows vloc + vgrp*4 + {0..3}, cols bgrp*4 + {0..3}
#pragma unroll
        for (int pair = 0; pair < 2; pair++) {
            int v = vloc + vgrp * 4 + pair * 2;
            float b0 = bias[v], b1 = bias[v + 1];
#pragma unroll
            for (int j = 0; j < 4; j++) {
                int bcol = bgrp * 4 + j;
                float lo, hi; unpack2(acc2[pair][j], lo, hi);
                *(float2*)(obase + (size_t)bcol * VP + v) =
                    make_float2(lo + b0, hi + b1);
            }
        }
    }
}

// ---------------------------------------------------------------------------
// attn-weights output softmax
// ---------------------------------------------------------------------------
__global__ void softmax_out_kernel(float* __restrict__ attn_out) {
    int b = blockIdx.x, tid = threadIdx.x;
    __shared__ float sh[8];
    __shared__ float sval;
    float m = -1e30f;
    for (int l = tid; l < L; l += 256) m = fmaxf(m, g_scores[b * L + l]);
#pragma unroll
    for (int o = 16; o; o >>= 1) m = fmaxf(m, __shfl_xor_sync(0xffffffffu, m, o));
    if ((tid & 31) == 0) sh[tid >> 5] = m;
    __syncthreads();
    if (tid == 0) {
        float mm = sh[0];
        for (int j = 1; j < 8; j++) mm = fmaxf(mm, sh[j]);
        sval = mm;
    }
    __syncthreads();
    m = sval;
    float s = 0.f;
    for (int l = tid; l < L; l += 256) s += expf(g_scores[b * L + l] - m);
    s = warp_sum(s);
    __syncthreads();
    if ((tid & 31) == 0) sh[tid >> 5] = s;
    __syncthreads();
    if (tid == 0) {
        float ss = 0.f;
        for (int j = 0; j < 8; j++) ss += sh[j];
        sval = ss;
    }
    __syncthreads();
    float inv = 1.f / sval;
    for (int l = tid; l < L; l += 256)
        attn_out[b * L + l] = expf(g_scores[b * L + l] - m) * inv;
}

// ---------------------------------------------------------------------------
extern "C" void kernel_launch(void* const* d_in, const int* in_sizes, int n_in,
                              void* d_out, int out_size) {
    const int*   seq         = (const int*)d_in[0];
    const float* last_hidden = (const float*)d_in[1];
    const float* enc         = (const float*)d_in[2];
    const float* emb         = (const float*)d_in[3];
    const float* w_ih        = (const float*)d_in[4];
    const float* w_hh        = (const float*)d_in[5];
    const float* b_ih        = (const float*)d_in[6];
    const float* b_hh        = (const float*)d_in[7];
    const float* concat_w    = (const float*)d_in[8];
    const float* concat_b    = (const float*)d_in[9];
    const float* owp         = (const float*)d_in[10];
    const float* obp         = (const float*)d_in[11];
    const float* owc         = (const float*)d_in[12];
    const float* obc         = (const float*)d_in[13];

    float* out        = (float*)d_out;
    float* out_hidden = out + (size_t)B * (VP + VC);
    float* out_attn   = out_hidden + (size_t)B * H;

    cudaFuncSetAttribute(gemm_part,     cudaFuncAttributeMaxDynamicSharedMemorySize, SM_GEMM3);
    cudaFuncSetAttribute(logits_hybrid, cudaFuncAttributeMaxDynamicSharedMemorySize, SM_LOG);

    float* gatep; cudaGetSymbolAddress((void**)&gatep, g_gatep);
    float* xh;    cudaGetSymbolAddress((void**)&xh, g_xh);
    float* hc;    cudaGetSymbolAddress((void**)&hc, g_hc);
    float* cpart; cudaGetSymbolAddress((void**)&cpart, g_cpart);

    pack_xh_kernel<<<B, 256>>>(seq, last_hidden, emb);
    gemm_part<<<dim3(48, GRU_SPLITS), 256, SM_GEMM3>>>(
        w_ih, w_hh, xh, xh + (size_t)B * H, gatep,
        H, H / GRU_SPLITS, 24, GRU_ROWS);
    gru_gate_kernel<<<H / 4, 256>>>(last_hidden, b_ih, b_hh, out_hidden);
    flash2_kernel<<<dim3(B, CS), 256>>>(enc);          // 4th: profiled
    ctx_combine2_kernel<<<B, 256>>>();
    gemm_part<<<dim3(8, CAT_SPLITS), 256, SM_GEMM3>>>(
        concat_w, nullptr, hc, nullptr, cpart,
        2 * H, 2 * H / CAT_SPLITS, 0, CAT_ROWS);
    cat_reduce_kernel<<<H / 4, 256>>>(concat_b);
    logits_hybrid<<<750, 256, SM_LOG>>>(owp, obp, owc, obc, out);
    softmax_out_kernel<<<B, 256>>>(out_attn);
}

// round 12
// speedup vs baseline: 3.0114x; 3.0114x over previous
#include <cuda_runtime.h>
#include <cuda_fp16.h>
#include <math.h>
#include <stdint.h>

#define H  1024
#define B  64
#define L  1024
#define VP 32000
#define VC 32000

// ---- flash attention config ----
#define CS   8
#define LPW  (L / CS / 8)
#define NPART 64

// ---- tf32 GEMM config (gru/concat) ----
#define TVL   128
#define KCL   32
#define PITCH 36
#define SM_GEMM3 ((2 * 2 * TVL * PITCH + 2 * 2 * B * PITCH) * 4)

// ---- logits fp16 GEMM config ----
#define WPITCH 40                       // W tile pitch (floats)
#define XPITCH 40                       // X tile pitch (halves)
#define STAGES 3
#define STG_BYTES (TVL * WPITCH * 4 + B * XPITCH * 2)   // 20480 + 5120
#define SM_LOG (STAGES * STG_BYTES)     // 76800

#define GRU_ROWS   6144
#define GRU_SPLITS 2
#define CAT_ROWS   1024
#define CAT_SPLITS 4

// ---- scratch ----
__device__ __align__(16) float g_xh[2 * B * H];
__device__ __align__(16) float g_gatep[GRU_SPLITS * GRU_ROWS * B];
__device__ __align__(16) float g_hnew[B * H];
__device__ __align__(16) float g_hc[B * 2 * H];
__device__ __align__(16) float g_scores[B * L];
__device__ __align__(16) float g_ctxpart[B * NPART * H];
__device__ float g_pm[B * NPART];
__device__ float g_ps[B * NPART];
__device__ __align__(16) float g_cpart[CAT_SPLITS * CAT_ROWS * B];
__device__ __align__(16) __half g_concat_h[B * H];   // fp16 X for logits

__device__ __forceinline__ float warp_sum(float v) {
#pragma unroll
    for (int o = 16; o; o >>= 1) v += __shfl_xor_sync(0xffffffffu, v, o);
    return v;
}
__device__ __forceinline__ float f2tf32f(float x) {
    uint32_t u; asm("cvt.rna.tf32.f32 %0, %1;" : "=r"(u) : "f"(x));
    return __uint_as_float(u);
}
__device__ __forceinline__ void mma_tf32(float* c, const uint32_t* a,
                                         uint32_t b0, uint32_t b1) {
    asm volatile(
        "mma.sync.aligned.m16n8k8.row.col.f32.tf32.tf32.f32 "
        "{%0,%1,%2,%3}, {%4,%5,%6,%7}, {%8,%9}, {%0,%1,%2,%3};"
        : "+f"(c[0]), "+f"(c[1]), "+f"(c[2]), "+f"(c[3])
        : "r"(a[0]), "r"(a[1]), "r"(a[2]), "r"(a[3]), "r"(b0), "r"(b1));
}
__device__ __forceinline__ void mma_f16(float* c, const uint32_t* a,
                                        uint32_t b0, uint32_t b1) {
    asm volatile(
        "mma.sync.aligned.m16n8k16.row.col.f32.f16.f16.f32 "
        "{%0,%1,%2,%3}, {%4,%5,%6,%7}, {%8,%9}, {%0,%1,%2,%3};"
        : "+f"(c[0]), "+f"(c[1]), "+f"(c[2]), "+f"(c[3])
        : "r"(a[0]), "r"(a[1]), "r"(a[2]), "r"(a[3]), "r"(b0), "r"(b1));
}
// pack two fp32 into f16x2: low = lo, high = hi
__device__ __forceinline__ uint32_t h2pack(float lo, float hi) {
    uint32_t r; asm("cvt.rn.f16x2.f32 %0, %1, %2;" : "=r"(r) : "f"(hi), "f"(lo));
    return r;
}
__device__ __forceinline__ void cp_async16(uint32_t dst, const void* src) {
    asm volatile("cp.async.cg.shared.global [%0], [%1], 16;" :: "r"(dst), "l"(src));
}
#define CP_COMMIT() asm volatile("cp.async.commit_group;" ::: "memory")
#define CP_WAIT(n)  asm volatile("cp.async.wait_group %0;" :: "n"(n) : "memory")

// ---------------------------------------------------------------------------
// 0) pack x and h_prev
// ---------------------------------------------------------------------------
__global__ void pack_xh_kernel(const int* __restrict__ seq,
                               const float* __restrict__ hprev,
                               const float* __restrict__ emb) {
    int b = blockIdx.x, tid = threadIdx.x;
    ((float4*)(g_xh + (size_t)b * H))[tid] =
        ((const float4*)(emb + (size_t)seq[b] * H))[tid];
    ((float4*)(g_xh + (size_t)(B + b) * H))[tid] =
        ((const float4*)(hprev + (size_t)b * H))[tid];
}

// ---------------------------------------------------------------------------
// Generic SPLIT-3 tf32 GEMM (R10, measured-good accuracy)
// ---------------------------------------------------------------------------
__global__ __launch_bounds__(256) void gemm_part(
        const float* __restrict__ A0, const float* __restrict__ A1,
        const float* __restrict__ X0, const float* __restrict__ X1,
        float* __restrict__ outp, int ldA, int kPerSplit, int halfBlocks,
        int totalRows) {
    extern __shared__ float smf[];
    float* Wt = smf;
    float* Xt = smf + 2 * 2 * TVL * PITCH;

    int tid = threadIdx.x;
    int wid = tid >> 5, lane = tid & 31;
    int grp = lane >> 2, tig = lane & 3;
    int warpM = wid & 3, warpN = wid >> 2;

    const float* A = A0; const float* X = X0;
    int blk = blockIdx.x;
    int outRowBase = blk * TVL;
    if (halfBlocks > 0 && blk >= halfBlocks) { A = A1; X = X1; blk -= halfBlocks; }
    int a0 = blk * TVL;
    int kOff = blockIdx.y * kPerSplit;
    int nt = kPerSplit / KCL;

#define WP_(buf, part) (Wt + ((buf) * 2 + (part)) * TVL * PITCH)
#define XP_(buf, part) (Xt + ((buf) * 2 + (part)) * B * PITCH)

    float acc[2][4][4];
#pragma unroll
    for (int i = 0; i < 2; i++)
#pragma unroll
        for (int j = 0; j < 4; j++)
#pragma unroll
            for (int q = 0; q < 4; q++) acc[i][j][q] = 0.f;

#pragma unroll
    for (int r = 0; r < 4; r++) {
        int f = tid + r * 256;
        int v = f >> 3, kq = f & 7;
        float4 w4 = *(const float4*)(A + (size_t)(a0 + v) * ldA + kOff + kq * 4);
        float hx = f2tf32f(w4.x), hy = f2tf32f(w4.y), hz = f2tf32f(w4.z), hw = f2tf32f(w4.w);
        *(float4*)&WP_(0, 0)[v * PITCH + kq * 4] = make_float4(hx, hy, hz, hw);
        *(float4*)&WP_(0, 1)[v * PITCH + kq * 4] =
            make_float4(f2tf32f(w4.x - hx), f2tf32f(w4.y - hy),
                        f2tf32f(w4.z - hz), f2tf32f(w4.w - hw));
    }
#pragma unroll
    for (int r = 0; r < 2; r++) {
        int f = tid + r * 256;
        int xb = f >> 3, kq = f & 7;
        float4 x4 = *(const float4*)(X + (size_t)xb * ldA + kOff + kq * 4);
        float hx = f2tf32f(x4.x), hy = f2tf32f(x4.y), hz = f2tf32f(x4.z), hw = f2tf32f(x4.w);
        *(float4*)&XP_(0, 0)[xb * PITCH + kq * 4] = make_float4(hx, hy, hz, hw);
        *(float4*)&XP_(0, 1)[xb * PITCH + kq * 4] =
            make_float4(f2tf32f(x4.x - hx), f2tf32f(x4.y - hy),
                        f2tf32f(x4.z - hz), f2tf32f(x4.w - hw));
    }
    __syncthreads();

    for (int t = 0; t < nt; t++) {
        int cur = t & 1;
        float* WH = WP_(cur, 0); float* WL = WP_(cur, 1);
        float* XH = XP_(cur, 0); float* XL = XP_(cur, 1);
        float4 wpre[4], xpre[2];
        if (t + 1 < nt) {
            int kc = kOff + (t + 1) * KCL;
#pragma unroll
            for (int r = 0; r < 4; r++) {
                int f = tid + r * 256;
                int v = f >> 3, kq = f & 7;
                wpre[r] = *(const float4*)(A + (size_t)(a0 + v) * ldA + kc + kq * 4);
            }
#pragma unroll
            for (int r = 0; r < 2; r++) {
                int f = tid + r * 256;
                int xb = f >> 3, kq = f & 7;
                xpre[r] = *(const float4*)(X + (size_t)xb * ldA + kc + kq * 4);
            }
        }
#pragma unroll
        for (int ks = 0; ks < KCL / 8; ks++) {
            int k0 = ks * 8 + tig;
            uint32_t aH[2][4], aL[2][4];
#pragma unroll
            for (int mf = 0; mf < 2; mf++) {
                int mm = warpM * 32 + mf * 16 + grp;
                aH[mf][0] = __float_as_uint(WH[mm * PITCH + k0]);
                aH[mf][1] = __float_as_uint(WH[(mm + 8) * PITCH + k0]);
                aH[mf][2] = __float_as_uint(WH[mm * PITCH + k0 + 4]);
                aH[mf][3] = __float_as_uint(WH[(mm + 8) * PITCH + k0 + 4]);
                aL[mf][0] = __float_as_uint(WL[mm * PITCH + k0]);
                aL[mf][1] = __float_as_uint(WL[(mm + 8) * PITCH + k0]);
                aL[mf][2] = __float_as_uint(WL[mm * PITCH + k0 + 4]);
                aL[mf][3] = __float_as_uint(WL[(mm + 8) * PITCH + k0 + 4]);
            }
#pragma unroll
            for (int nf = 0; nf < 4; nf++) {
                int n = warpN * 32 + nf * 8 + grp;
                uint32_t bH0 = __float_as_uint(XH[n * PITCH + k0]);
                uint32_t bH1 = __float_as_uint(XH[n * PITCH + k0 + 4]);
                uint32_t bL0 = __float_as_uint(XL[n * PITCH + k0]);
                uint32_t bL1 = __float_as_uint(XL[n * PITCH + k0 + 4]);
#pragma unroll
                for (int mf = 0; mf < 2; mf++) {
                    mma_tf32(acc[mf][nf], aH[mf], bH0, bH1);
                    mma_tf32(acc[mf][nf], aH[mf], bL0, bL1);
                    mma_tf32(acc[mf][nf], aL[mf], bH0, bH1);
                }
            }
        }
        if (t + 1 < nt) {
            int nxt = cur ^ 1;
#pragma unroll
            for (int r = 0; r < 4; r++) {
                int f = tid + r * 256;
                int v = f >> 3, kq = f & 7;
                float hx = f2tf32f(wpre[r].x), hy = f2tf32f(wpre[r].y);
                float hz = f2tf32f(wpre[r].z), hw = f2tf32f(wpre[r].w);
                *(float4*)&WP_(nxt, 0)[v * PITCH + kq * 4] = make_float4(hx, hy, hz, hw);
                *(float4*)&WP_(nxt, 1)[v * PITCH + kq * 4] =
                    make_float4(f2tf32f(wpre[r].x - hx), f2tf32f(wpre[r].y - hy),
                                f2tf32f(wpre[r].z - hz), f2tf32f(wpre[r].w - hw));
            }
#pragma unroll
            for (int r = 0; r < 2; r++) {
                int f = tid + r * 256;
                int xb = f >> 3, kq = f & 7;
                float hx = f2tf32f(xpre[r].x), hy = f2tf32f(xpre[r].y);
                float hz = f2tf32f(xpre[r].z), hw = f2tf32f(xpre[r].w);
                *(float4*)&XP_(nxt, 0)[xb * PITCH + kq * 4] = make_float4(hx, hy, hz, hw);
                *(float4*)&XP_(nxt, 1)[xb * PITCH + kq * 4] =
                    make_float4(f2tf32f(xpre[r].x - hx), f2tf32f(xpre[r].y - hy),
                                f2tf32f(xpre[r].z - hz), f2tf32f(xpre[r].w - hw));
            }
        }
        __syncthreads();
    }
#undef WP_
#undef XP_

    float* o = outp + (size_t)blockIdx.y * totalRows * B;
#pragma unroll
    for (int mf = 0; mf < 2; mf++) {
        int vr = outRowBase + warpM * 32 + mf * 16 + grp;
#pragma unroll
        for (int nf = 0; nf < 4; nf++) {
            int bcol = warpN * 32 + nf * 8 + 2 * tig;
            o[(size_t)vr * B + bcol]           = acc[mf][nf][0];
            o[(size_t)vr * B + bcol + 1]       = acc[mf][nf][1];
            o[(size_t)(vr + 8) * B + bcol]     = acc[mf][nf][2];
            o[(size_t)(vr + 8) * B + bcol + 1] = acc[mf][nf][3];
        }
    }
}

// ---------------------------------------------------------------------------
// gate combine -> h_new
// ---------------------------------------------------------------------------
__global__ void gru_gate_kernel(const float* __restrict__ hprev,
                                const float* __restrict__ b_ih,
                                const float* __restrict__ b_hh,
                                float* __restrict__ hidden_out) {
    int tid = threadIdx.x;
    int b = tid & 63;
    int i = blockIdx.x * 4 + (tid >> 6);
#define GP(row) (g_gatep[(size_t)(row) * B + b] + \
                 g_gatep[(size_t)(GRU_ROWS + (row)) * B + b])
    float gir = GP(i),          giz = GP(H + i),      gin = GP(2 * H + i);
    float ghr = GP(3 * H + i),  ghz = GP(4 * H + i),  ghn = GP(5 * H + i);
#undef GP
    float r = 1.f / (1.f + expf(-(gir + b_ih[i] + ghr + b_hh[i])));
    float z = 1.f / (1.f + expf(-(giz + b_ih[H + i] + ghz + b_hh[H + i])));
    float n = tanhf(gin + b_ih[2 * H + i] + r * (ghn + b_hh[2 * H + i]));
    float hv = hprev[(size_t)b * H + i];
    float hn = (1.f - z) * n + z * hv;
    g_hnew[(size_t)b * H + i] = hn;
    g_hc[(size_t)b * 2 * H + i] = hn;
    hidden_out[(size_t)b * H + i] = hn;
}

// ---------------------------------------------------------------------------
// flash attention (measured 47us @ 76% DRAM)
// ---------------------------------------------------------------------------
__global__ __launch_bounds__(256) void flash2_kernel(const float* __restrict__ enc) {
    int b = blockIdx.x, ch = blockIdx.y;
    int w = threadIdx.x >> 5, lane = threadIdx.x & 31;
    int l0 = ch * (L / CS) + w * LPW;

    const float4* hb = (const float4*)(g_hnew + (size_t)b * H);
    float4 h[8];
#pragma unroll
    for (int q = 0; q < 8; q++) h[q] = hb[lane + q * 32];

    float4 acc[8];
#pragma unroll
    for (int q = 0; q < 8; q++) acc[q] = make_float4(0.f, 0.f, 0.f, 0.f);
    float m = -1e30f, ssum = 0.f;

    for (int j = 0; j < LPW; j++) {
        int l = l0 + j;
        const float4* er = (const float4*)(enc + ((size_t)l * B + b) * H);
        float4 e[8];
        float d = 0.f;
#pragma unroll
        for (int q = 0; q < 8; q++) {
            e[q] = er[lane + q * 32];
            d += e[q].x * h[q].x + e[q].y * h[q].y + e[q].z * h[q].z + e[q].w * h[q].w;
        }
        d = warp_sum(d);
        if (lane == 0) g_scores[b * L + l] = d;
        float nm = fmaxf(m, d);
        float sc = expf(m - nm);
        float p = expf(d - nm);
        ssum = ssum * sc + p;
#pragma unroll
        for (int q = 0; q < 8; q++) {
            acc[q].x = acc[q].x * sc + p * e[q].x;
            acc[q].y = acc[q].y * sc + p * e[q].y;
            acc[q].z = acc[q].z * sc + p * e[q].z;
            acc[q].w = acc[q].w * sc + p * e[q].w;
        }
        m = nm;
    }

    int pidx = b * NPART + ch * 8 + w;
    float4* pp = (float4*)(g_ctxpart + (size_t)pidx * H);
#pragma unroll
    for (int q = 0; q < 8; q++) pp[lane + q * 32] = acc[q];
    if (lane == 0) { g_pm[pidx] = m; g_ps[pidx] = ssum; }
}

__global__ void ctx_combine2_kernel() {
    int b = blockIdx.x, tid = threadIdx.x;
    __shared__ float sm[NPART], sw[NPART];
    if (tid < NPART) sm[tid] = g_pm[b * NPART + tid];
    __syncthreads();
    float gm = -1e30f;
#pragma unroll 8
    for (int c = 0; c < NPART; c++) gm = fmaxf(gm, sm[c]);
    if (tid < NPART) sw[tid] = expf(sm[tid] - gm);
    __syncthreads();
    float S = 0.f;
#pragma unroll 8
    for (int c = 0; c < NPART; c++) S += g_ps[b * NPART + c] * sw[c];
    float inv = 1.f / S;
    float4 a = make_float4(0.f, 0.f, 0.f, 0.f);
    for (int c = 0; c < NPART; c++) {
        float wgt = sw[c];
        float4 p = ((const float4*)(g_ctxpart + ((size_t)(b * NPART + c)) * H))[tid];
        a.x += wgt * p.x; a.y += wgt * p.y; a.z += wgt * p.z; a.w += wgt * p.w;
    }
    a.x *= inv; a.y *= inv; a.z *= inv; a.w *= inv;
    ((float4*)(g_hc + (size_t)b * 2 * H + H))[tid] = a;
}

// ---------------------------------------------------------------------------
// concat reduce + tanh; stores g_concat_h as fp16 for the logits GEMM
// ---------------------------------------------------------------------------
__global__ void cat_reduce_kernel(const float* __restrict__ cb) {
    int tid = threadIdx.x;
    int b = tid & 63;
    int i = blockIdx.x * 4 + (tid >> 6);
    float s = 0.f;
#pragma unroll
    for (int y = 0; y < CAT_SPLITS; y++)
        s += g_cpart[(size_t)(y * CAT_ROWS + i) * B + b];
    g_concat_h[(size_t)b * H + i] = __float2half_rn(tanhf(s + cb[i]));
}

// ---------------------------------------------------------------------------
// logits: fp16 m16n8k16 mma.sync GEMM, 3-stage cp.async pipeline.
// W raw fp32 in smem -> cvt.rn.f16x2 at fragment load; X pre-converted fp16.
// Half the MMA instructions of the tf32 version at the same mantissa width.
// ---------------------------------------------------------------------------
__global__ __launch_bounds__(256) void logits_f16(
        const float* __restrict__ wp, const float* __restrict__ bp,
        const float* __restrict__ wc, const float* __restrict__ bc,
        float* __restrict__ out) {
    extern __shared__ char smc[];

    int tid = threadIdx.x;
    int wid = tid >> 5, lane = tid & 31;
    int grp = lane >> 2, tig = lane & 3;
    int warpM = wid & 3, warpN = wid >> 2;

    int v0 = blockIdx.x * TVL;
    const float* W; const float* bias; float* obase;
    if (v0 < VP) { W = wp; bias = bp; obase = out; }
    else { W = wc; bias = bc; obase = out + (size_t)B * VP; v0 -= VP; }

    float acc[2][4][4];
#pragma unroll
    for (int i = 0; i < 2; i++)
#pragma unroll
        for (int j = 0; j < 4; j++)
#pragma unroll
            for (int q = 0; q < 4; q++) acc[i][j][q] = 0.f;

    const int NT = H / KCL;   // 32

    auto issue = [&](int t, int slot) {
        char* base = smc + slot * STG_BYTES;
        float* Ws = (float*)base;
        __half* Xs = (__half*)(base + TVL * WPITCH * 4);
        int kc = t * KCL;
#pragma unroll
        for (int r = 0; r < 4; r++) {
            int f = tid + r * 256;
            int v = f >> 3, kq = f & 7;
            uint32_t dst = (uint32_t)__cvta_generic_to_shared(&Ws[v * WPITCH + kq * 4]);
            cp_async16(dst, W + (size_t)(v0 + v) * H + kc + kq * 4);
        }
        {
            int xb = tid >> 2, q = tid & 3;   // 64 rows x 4 chunks of 8 halves
            uint32_t dst = (uint32_t)__cvta_generic_to_shared(&Xs[xb * XPITCH + q * 8]);
            cp_async16(dst, g_concat_h + (size_t)xb * H + kc + q * 8);
        }
        CP_COMMIT();
    };

    issue(0, 0);
    issue(1, 1);

    for (int t = 0; t < NT; t++) {
        if (t + 2 < NT) { CP_WAIT(1); } else { CP_WAIT(0); }
        __syncthreads();
        if (t + 2 < NT) issue(t + 2, (t + 2) % STAGES);

        char* base = smc + (t % STAGES) * STG_BYTES;
        float* Wc = (float*)base;
        __half* Xc = (__half*)(base + TVL * WPITCH * 4);

#pragma unroll
        for (int ks = 0; ks < KCL / 16; ks++) {       // 2 k16 steps per tile
            int kf = ks * 16 + 2 * tig;               // A col base (floats)
            uint32_t a[2][4];
#pragma unroll
            for (int mf = 0; mf < 2; mf++) {
                int mm = warpM * 32 + mf * 16 + grp;
                float2 w00 = *(const float2*)&Wc[mm * WPITCH + kf];
                float2 w10 = *(const float2*)&Wc[(mm + 8) * WPITCH + kf];
                float2 w01 = *(const float2*)&Wc[mm * WPITCH + kf + 8];
                float2 w11 = *(const float2*)&Wc[(mm + 8) * WPITCH + kf + 8];
                a[mf][0] = h2pack(w00.x, w00.y);
                a[mf][1] = h2pack(w10.x, w10.y);
                a[mf][2] = h2pack(w01.x, w01.y);
                a[mf][3] = h2pack(w11.x, w11.y);
            }
#pragma unroll
            for (int nf = 0; nf < 4; nf++) {
                int n = warpN * 32 + nf * 8 + grp;
                uint32_t b0 = *(const uint32_t*)&Xc[n * XPITCH + ks * 16 + 2 * tig];
                uint32_t b1 = *(const uint32_t*)&Xc[n * XPITCH + ks * 16 + 2 * tig + 8];
                mma_f16(acc[0][nf], a[0], b0, b1);
                mma_f16(acc[1][nf], a[1], b0, b1);
            }
        }
        __syncthreads();
    }

#pragma unroll
    for (int mf = 0; mf < 2; mf++) {
        int vr = v0 + warpM * 32 + mf * 16 + grp;
        float b0 = bias[vr], b1 = bias[vr + 8];
#pragma unroll
        for (int nf = 0; nf < 4; nf++) {
            int bcol = warpN * 32 + nf * 8 + 2 * tig;
            obase[(size_t)bcol * VP + vr]           = acc[mf][nf][0] + b0;
            obase[(size_t)(bcol + 1) * VP + vr]     = acc[mf][nf][1] + b0;
            obase[(size_t)bcol * VP + vr + 8]       = acc[mf][nf][2] + b1;
            obase[(size_t)(bcol + 1) * VP + vr + 8] = acc[mf][nf][3] + b1;
        }
    }
}

// ---------------------------------------------------------------------------
// attn-weights output softmax
// ---------------------------------------------------------------------------
__global__ void softmax_out_kernel(float* __restrict__ attn_out) {
    int b = blockIdx.x, tid = threadIdx.x;
    __shared__ float sh[8];
    __shared__ float sval;
    float m = -1e30f;
    for (int l = tid; l < L; l += 256) m = fmaxf(m, g_scores[b * L + l]);
#pragma unroll
    for (int o = 16; o; o >>= 1) m = fmaxf(m, __shfl_xor_sync(0xffffffffu, m, o));
    if ((tid & 31) == 0) sh[tid >> 5] = m;
    __syncthreads();
    if (tid == 0) {
        float mm = sh[0];
        for (int j = 1; j < 8; j++) mm = fmaxf(mm, sh[j]);
        sval = mm;
    }
    __syncthreads();
    m = sval;
    float s = 0.f;
    for (int l = tid; l < L; l += 256) s += expf(g_scores[b * L + l] - m);
    s = warp_sum(s);
    __syncthreads();
    if ((tid & 31) == 0) sh[tid >> 5] = s;
    __syncthreads();
    if (tid == 0) {
        float ss = 0.f;
        for (int j = 0; j < 8; j++) ss += sh[j];
        sval = ss;
    }
    __syncthreads();
    float inv = 1.f / sval;
    for (int l = tid; l < L; l += 256)
        attn_out[b * L + l] = expf(g_scores[b * L + l] - m) * inv;
}

// ---------------------------------------------------------------------------
extern "C" void kernel_launch(void* const* d_in, const int* in_sizes, int n_in,
                              void* d_out, int out_size) {
    const int*   seq         = (const int*)d_in[0];
    const float* last_hidden = (const float*)d_in[1];
    const float* enc         = (const float*)d_in[2];
    const float* emb         = (const float*)d_in[3];
    const float* w_ih        = (const float*)d_in[4];
    const float* w_hh        = (const float*)d_in[5];
    const float* b_ih        = (const float*)d_in[6];
    const float* b_hh        = (const float*)d_in[7];
    const float* concat_w    = (const float*)d_in[8];
    const float* concat_b    = (const float*)d_in[9];
    const float* owp         = (const float*)d_in[10];
    const float* obp         = (const float*)d_in[11];
    const float* owc         = (const float*)d_in[12];
    const float* obc         = (const float*)d_in[13];

    float* out        = (float*)d_out;
    float* out_hidden = out + (size_t)B * (VP + VC);
    float* out_attn   = out_hidden + (size_t)B * H;

    cudaFuncSetAttribute(gemm_part,  cudaFuncAttributeMaxDynamicSharedMemorySize, SM_GEMM3);
    cudaFuncSetAttribute(logits_f16, cudaFuncAttributeMaxDynamicSharedMemorySize, SM_LOG);

    float* gatep; cudaGetSymbolAddress((void**)&gatep, g_gatep);
    float* xh;    cudaGetSymbolAddress((void**)&xh, g_xh);
    float* hc;    cudaGetSymbolAddress((void**)&hc, g_hc);
    float* cpart; cudaGetSymbolAddress((void**)&cpart, g_cpart);

    pack_xh_kernel<<<B, 256>>>(seq, last_hidden, emb);
    gemm_part<<<dim3(48, GRU_SPLITS), 256, SM_GEMM3>>>(
        w_ih, w_hh, xh, xh + (size_t)B * H, gatep,
        H, H / GRU_SPLITS, 24, GRU_ROWS);
    gru_gate_kernel<<<H / 4, 256>>>(last_hidden, b_ih, b_hh, out_hidden);
    flash2_kernel<<<dim3(B, CS), 256>>>(enc);          // 4th: profiled
    ctx_combine2_kernel<<<B, 256>>>();
    gemm_part<<<dim3(8, CAT_SPLITS), 256, SM_GEMM3>>>(
        concat_w, nullptr, hc, nullptr, cpart,
        2 * H, 2 * H / CAT_SPLITS, 0, CAT_ROWS);
    cat_reduce_kernel<<<H / 4, 256>>>(concat_b);
    logits_f16<<<(VP + VC) / TVL, 256, SM_LOG>>>(owp, obp, owc, obc, out);
    softmax_out_kernel<<<B, 256>>>(out_attn);
}